// round 13
// baseline (speedup 1.0000x reference)
#include <cuda_runtime.h>
#include <cuda_fp16.h>
#include <mma.h>
#include <math.h>

using namespace nvcuda;

#define NMAX 20000
#define NPAD 20224          // 158 * 128
#define EMAX 200000
#define GMAX 128
#define DH   32
#define EPW  4              // edges per warp in k_edge_msg

__device__ __half  g_h0[NPAD * DH];            // fp16 node feats; padding rows stay zero
__device__ __half  g_h1[NPAD * DH];
// G4: per node 136 uint4 = [4 quad-rows][32 lanes] uint4 (qq*32+o; component c = k-pair j=4qq+c,
// each half2 = (G[2j]. G[2j+1]) for output o) + 8 uint4 bias row (half2[32]: (biaspart, rootpart)).
__device__ uint4   g_G4[(size_t)NMAX * 136];
__device__ float   g_agg[NMAX * DH];
__device__ float   g_pooled[GMAX * DH];

#define FULLMASK 0xffffffffu

__device__ __forceinline__ float lrelu(float v) { return v > 0.f ? v : 0.01f * v; }

// ---------------- Kernel A: h0 = lrelu(x @ nfc_w + nfc_b) -> fp16 -----------
__global__ void k_node_in(const float* __restrict__ x, const float* __restrict__ w,
                          const float* __restrict__ b, __half* __restrict__ h0, int N) {
    int warp = (blockIdx.x * blockDim.x + threadIdx.x) >> 5;
    int lane = threadIdx.x & 31;
    if (warp >= N) return;
    const float* xr = x + (size_t)warp * 64;
    float x0 = xr[lane];
    float x1 = xr[32 + lane];
    float acc = b[lane];
#pragma unroll
    for (int i = 0; i < 32; i++) {
        float xv = __shfl_sync(FULLMASK, x0, i);
        acc = fmaf(xv, w[i * 32 + lane], acc);
    }
#pragma unroll
    for (int i = 0; i < 32; i++) {
        float xv = __shfl_sync(FULLMASK, x1, i);
        acc = fmaf(xv, w[(32 + i) * 32 + lane], acc);
    }
    h0[warp * 32 + lane] = __float2half_rn(lrelu(acc));
}

// ---------------- Kernel C: tensor-core precompute of G4 --------------------
// GEMM G'[n, m] = sum_i h[n,i] * B[i,m], permuted B so adjacent cols are half2 pairs:
//   m = j*64 + 2*o + p:  j<16 -> w2[(2j+p)*1024 + i*32 + o]
//                        j=16 -> p==0: b2[i*32+o], p==1: root[i*32+o]
// Epilogue remaps pair index P=j*32+o into the quad-packed G4 layout.
__global__ void k_precompute_mma(const __half* __restrict__ hA,
                                 const float* __restrict__ w2, const float* __restrict__ b2,
                                 const float* __restrict__ root,
                                 uint4* __restrict__ G4, int N) {
    extern __shared__ __half Bs[];   // [32][1104]
    int tid = threadIdx.x;
    for (int idx = tid; idx < 32 * 1024; idx += 256) {
        int k = idx >> 10;              // w2 row 0..31
        int rem = idx & 1023;
        int i = rem >> 5, o = rem & 31;
        int m = (k >> 1) * 64 + 2 * o + (k & 1);
        Bs[i * 1104 + m] = __float2half_rn(w2[idx]);   // coalesced read
    }
    for (int idx = tid; idx < 1024; idx += 256) {
        int i = idx >> 5, o = idx & 31;
        Bs[i * 1104 + 1024 + 2 * o]     = __float2half_rn(b2[idx]);
        Bs[i * 1104 + 1024 + 2 * o + 1] = __float2half_rn(root[idx]);
    }
    __syncthreads();

    int w = tid >> 5, lane = tid & 31;
    int g = lane >> 2, t = lane & 3;

    int ngroups = (N + 127) / 128;
    for (int grp = blockIdx.x; grp < ngroups; grp += gridDim.x) {
        int n0 = grp * 128 + w * 16;
        wmma::fragment<wmma::matrix_a, 16, 16, 16, __half, wmma::row_major> a0, a1;
        wmma::load_matrix_sync(a0, hA + (size_t)n0 * 32, 32);
        wmma::load_matrix_sync(a1, hA + (size_t)n0 * 32 + 16, 32);

        int r0 = n0 + g, r1 = n0 + g + 8;
        __half2* p0 = (__half2*)(G4 + (size_t)r0 * 136);
        __half2* p1 = (__half2*)(G4 + (size_t)r1 * 136);

#pragma unroll 4
        for (int jb = 0; jb < 68; jb++) {
            wmma::fragment<wmma::matrix_b, 16, 16, 16, __half, wmma::row_major> b0f, b1f;
            wmma::fragment<wmma::accumulator, 16, 16, 16, float> cf;
            wmma::fill_fragment(cf, 0.f);
            wmma::load_matrix_sync(b0f, Bs + jb * 16, 1104);
            wmma::load_matrix_sync(b1f, Bs + 16 * 1104 + jb * 16, 1104);
            wmma::mma_sync(cf, a0, b0f, cf);
            wmma::mma_sync(cf, a1, b1f, cf);
            // fp32 C frag: x0,x1=row g cols(2t,2t+1); x2,x3=row g+8; x4..7 = cols+8.
            int P0 = jb * 8 + t;          // pair index; P1 = P0 + 4 (same j, o+4)
            int a0i, a1i;
            if (jb < 64) {
                int j = P0 >> 5, o0 = P0 & 31;
                a0i = (j >> 2) * 128 + o0 * 4 + (j & 3);
                a1i = a0i + 16;           // o0+4 -> +16 half2
            } else {
                a0i = P0;                 // bias row: half2 index 512+o == P0
                a1i = P0 + 4;
            }
            if (r0 < N) {
                p0[a0i] = __floats2half2_rn(cf.x[0], cf.x[1]);
                p0[a1i] = __floats2half2_rn(cf.x[4], cf.x[5]);
            }
            if (r1 < N) {
                p1[a0i] = __floats2half2_rn(cf.x[2], cf.x[3]);
                p1[a1i] = __floats2half2_rn(cf.x[6], cf.x[7]);
            }
        }
    }
}

// ---------------- agg init: rootpart (bias row .y) + bias -------------------
__global__ void k_agg_init(const uint4* __restrict__ G4, const float* __restrict__ bias,
                           float* __restrict__ agg, int N) {
    int idx = blockIdx.x * blockDim.x + threadIdx.x;
    if (idx >= N * 32) return;
    int n = idx >> 5, o = idx & 31;
    const __half2* p = (const __half2*)(G4 + (size_t)n * 136);
    agg[idx] = __high2float(p[512 + o]) + bias[o];
}

// ---------------- Kernel D: fused edge MLP + message + scatter-add ----------
__global__ void k_edge_msg(const int* __restrict__ ei, const float* __restrict__ ea,
                           const float* __restrict__ w1, const float* __restrict__ b1,
                           const uint4* __restrict__ G4, float* __restrict__ agg, int E) {
    int tid = threadIdx.x;
    int lane = tid & 31;
    int warpg = (blockIdx.x * blockDim.x + tid) >> 5;

    float w1col[16];
#pragma unroll
    for (int j = 0; j < 16; j++) w1col[j] = __ldg(&w1[j * 32 + lane]);
    float b1l = __ldg(&b1[lane]);

    int ebase = warpg * EPW;
#pragma unroll
    for (int ee = 0; ee < EPW; ee++) {
        int e = ebase + ee;
        if (e >= E) return;
        int src = __ldg(&ei[e]);
        int dst = __ldg(&ei[E + e]);

        // ea pairs: even lane 2j holds half2(ea[2j], ea[2j+1])
        float eav = (lane < 16) ? __ldg(&ea[(size_t)e * 16 + lane]) : 0.f;
        float eao = __shfl_xor_sync(FULLMASK, eav, 1);
        __half2 ea2 = (lane & 1) ? __floats2half2_rn(eao, eav) : __floats2half2_rn(eav, eao);
        unsigned eu = *(unsigned*)&ea2;

        // hidden MLP: a[lane] = b1[lane] + sum_j ea[j]*w1[j][lane]
        float a = b1l;
#pragma unroll
        for (int j = 0; j < 8; j++) {
            unsigned u = __shfl_sync(FULLMASK, eu, 2 * j);
            float2 f = __half22float2(*(__half2*)&u);
            a = fmaf(f.x, w1col[2 * j], a);
            a = fmaf(f.y, w1col[2 * j + 1], a);
        }
        float rv = fmaxf(a, 0.f);

        // rv pairs: lane 2m holds half2(rh[2m], rh[2m+1])
        float ro = __shfl_xor_sync(FULLMASK, rv, 1);
        __half2 rp2 = (lane & 1) ? __floats2half2_rn(ro, rv) : __floats2half2_rn(rv, ro);
        unsigned rp = *(unsigned*)&rp2;

        const uint4* gq = G4 + (size_t)src * 136;
        __half2 hb = ((const __half2*)gq)[512 + lane];
        float m0 = __low2float(hb);     // bias-part
        float m1 = 0.f;
#pragma unroll
        for (int qq = 0; qq < 4; qq++) {
            uint4 gg = __ldg(&gq[qq * 32 + lane]);
#pragma unroll
            for (int c = 0; c < 4; c++) {
                int j = 4 * qq + c;
                unsigned gu = (c == 0) ? gg.x : (c == 1) ? gg.y : (c == 2) ? gg.z : gg.w;
                unsigned u = __shfl_sync(FULLMASK, rp, 2 * j);
                float2 r2 = __half22float2(*(__half2*)&u);
                float2 f = __half22float2(*(__half2*)&gu);
                m0 = fmaf(r2.x, f.x, m0);
                m1 = fmaf(r2.y, f.y, m1);
            }
        }
        atomicAdd(&agg[(size_t)dst * 32 + lane], m0 + m1);
    }
}

// ---------------- Kernel E1: h = lrelu(agg) -> fp16 -------------------------
__global__ void k_act(const float* __restrict__ agg, __half* __restrict__ h, int total) {
    int idx = blockIdx.x * blockDim.x + threadIdx.x;
    if (idx >= total) return;
    h[idx] = __float2half_rn(lrelu(agg[idx]));
}

__global__ void k_zero(float* __restrict__ p, int total) {
    int idx = blockIdx.x * blockDim.x + threadIdx.x;
    if (idx < total) p[idx] = 0.f;
}

// ---------------- Kernel E2: atom_embs = lrelu(agg); pool into graphs -------
__global__ void k_act_pool(const float* __restrict__ agg, const int* __restrict__ batch,
                           float* __restrict__ atom_out, float* __restrict__ pooled, int N) {
    int idx = blockIdx.x * blockDim.x + threadIdx.x;
    if (idx >= N * 32) return;
    int n = idx >> 5;
    int o = idx & 31;
    float v = lrelu(agg[idx]);
    atom_out[idx] = v;
    atomicAdd(&pooled[batch[n] * 32 + o], v);
}

// ---------------- Kernel F: normalize pooled rows + final fc ----------------
__global__ void k_final(const float* __restrict__ pooled, const float* __restrict__ fcw,
                        const float* __restrict__ fcb, float* __restrict__ out, int G) {
    int warp = (blockIdx.x * blockDim.x + threadIdx.x) >> 5;
    int lane = threadIdx.x & 31;
    if (warp >= G) return;
    float p = pooled[warp * 32 + lane];
    float ss = p * p;
#pragma unroll
    for (int off = 16; off > 0; off >>= 1) ss += __shfl_xor_sync(FULLMASK, ss, off);
    float nrm = sqrtf(ss);
    float d = fmaxf(nrm, 1e-12f);
    float pn = p / d;
    float acc = fcb[lane];
#pragma unroll
    for (int jj = 0; jj < 32; jj++) {
        float pv = __shfl_sync(FULLMASK, pn, jj);
        acc = fmaf(pv, fcw[jj * 32 + lane], acc);
    }
    out[warp * 32 + lane] = acc;
}

extern "C" void kernel_launch(void* const* d_in, const int* in_sizes, int n_in,
                              void* d_out, int out_size) {
    const float* x        = (const float*)d_in[0];
    const int*   ei       = (const int*)  d_in[1];
    const float* ea       = (const float*)d_in[2];
    const int*   batch    = (const int*)  d_in[3];
    const float* nfc_w    = (const float*)d_in[5];
    const float* nfc_b    = (const float*)d_in[6];
    const float* e1w1     = (const float*)d_in[7];
    const float* e1b1     = (const float*)d_in[8];
    const float* e1w2     = (const float*)d_in[9];
    const float* e1b2     = (const float*)d_in[10];
    const float* root1    = (const float*)d_in[11];
    const float* bias1    = (const float*)d_in[12];
    const float* e2w1     = (const float*)d_in[13];
    const float* e2b1     = (const float*)d_in[14];
    const float* e2w2     = (const float*)d_in[15];
    const float* e2b2     = (const float*)d_in[16];
    const float* root2    = (const float*)d_in[17];
    const float* bias2    = (const float*)d_in[18];
    const float* fcw      = (const float*)d_in[19];
    const float* fcb      = (const float*)d_in[20];

    int N = in_sizes[0] / 64;
    int E = in_sizes[2] / 16;
    const int G = GMAX;

    float* outp = (float*)d_out;                 // [G,32]
    float* atom_out = (float*)d_out + G * 32;    // [N,32]

    __half *h0, *h1;
    float *agg, *pooled;
    uint4* G4;
    cudaGetSymbolAddress((void**)&h0,     g_h0);
    cudaGetSymbolAddress((void**)&h1,     g_h1);
    cudaGetSymbolAddress((void**)&G4,     g_G4);
    cudaGetSymbolAddress((void**)&agg,    g_agg);
    cudaGetSymbolAddress((void**)&pooled, g_pooled);

    const int smemC = 32 * 1104 * sizeof(__half);   // 70656 B
    cudaFuncSetAttribute(k_precompute_mma, cudaFuncAttributeMaxDynamicSharedMemorySize, smemC);

    int ngroups = (N + 127) / 128;
    int egrid = (E + EPW * 8 - 1) / (EPW * 8);

    k_node_in<<<(N + 7) / 8, 256>>>(x, nfc_w, nfc_b, h0, N);

    // ---- layer 1 ----
    k_precompute_mma<<<ngroups, 256, smemC>>>(h0, e1w2, e1b2, root1, G4, N);
    k_agg_init<<<(N * 32 + 255) / 256, 256>>>(G4, bias1, agg, N);
    k_edge_msg<<<egrid, 256>>>(ei, ea, e1w1, e1b1, G4, agg, E);
    k_act<<<(N * 32 + 255) / 256, 256>>>(agg, h1, N * 32);

    // ---- layer 2 ----
    k_precompute_mma<<<ngroups, 256, smemC>>>(h1, e2w2, e2b2, root2, G4, N);
    k_agg_init<<<(N * 32 + 255) / 256, 256>>>(G4, bias2, agg, N);
    k_edge_msg<<<egrid, 256>>>(ei, ea, e2w1, e2b1, G4, agg, E);

    // pooling + outputs
    k_zero<<<(G * 32 + 255) / 256, 256>>>(pooled, G * 32);
    k_act_pool<<<(N * 32 + 255) / 256, 256>>>(agg, batch, atom_out, pooled, N);
    k_final<<<(G + 3) / 4, 128>>>(pooled, fcw, fcb, outp, G);
}

// round 15
// speedup vs baseline: 1.1249x; 1.1249x over previous
#include <cuda_runtime.h>
#include <cuda_fp16.h>
#include <mma.h>
#include <math.h>

using namespace nvcuda;

#define NMAX 20000
#define NPAD 20224          // 158 * 128
#define EMAX 200000
#define GMAX 128
#define DH   32
#define NPAIR 2             // edge-pairs per warp iteration (4 edges/warp)

__device__ __half  g_h0[NPAD * DH];            // fp16 node feats; padding rows stay zero
__device__ __half  g_h1[NPAD * DH];
__device__ __half2 g_G2[(size_t)NMAX * 544];   // [N][17][32] half2; pair j<16=(k=2j,2j+1); j=16=(biaspart, rootpart)
__device__ float   g_agg[NMAX * DH];
__device__ float   g_pooled[GMAX * DH];

#define FULLMASK 0xffffffffu

__device__ __forceinline__ float lrelu(float v) { return v > 0.f ? v : 0.01f * v; }

// ---------------- Kernel A: h0 = lrelu(x @ nfc_w + nfc_b) -> fp16 -----------
__global__ void k_node_in(const float* __restrict__ x, const float* __restrict__ w,
                          const float* __restrict__ b, __half* __restrict__ h0, int N) {
    int warp = (blockIdx.x * blockDim.x + threadIdx.x) >> 5;
    int lane = threadIdx.x & 31;
    if (warp >= N) return;
    const float* xr = x + (size_t)warp * 64;
    float x0 = xr[lane];
    float x1 = xr[32 + lane];
    float acc = b[lane];
#pragma unroll
    for (int i = 0; i < 32; i++) {
        float xv = __shfl_sync(FULLMASK, x0, i);
        acc = fmaf(xv, w[i * 32 + lane], acc);
    }
#pragma unroll
    for (int i = 0; i < 32; i++) {
        float xv = __shfl_sync(FULLMASK, x1, i);
        acc = fmaf(xv, w[(32 + i) * 32 + lane], acc);
    }
    h0[warp * 32 + lane] = __float2half_rn(lrelu(acc));
}

// ---------------- Kernel C: tensor-core precompute of G2 (R12 version) ------
__global__ void k_precompute_mma(const __half* __restrict__ hA,
                                 const float* __restrict__ w2, const float* __restrict__ b2,
                                 const float* __restrict__ root,
                                 __half2* __restrict__ G2, int N) {
    extern __shared__ __half Bs[];   // [32][1104]
    int tid = threadIdx.x;
    for (int idx = tid; idx < 32 * 1024; idx += 256) {
        int k = idx >> 10;              // w2 row 0..31
        int rem = idx & 1023;
        int i = rem >> 5, o = rem & 31;
        int m = (k >> 1) * 64 + 2 * o + (k & 1);
        Bs[i * 1104 + m] = __float2half_rn(w2[idx]);   // coalesced read
    }
    for (int idx = tid; idx < 1024; idx += 256) {
        int i = idx >> 5, o = idx & 31;
        Bs[i * 1104 + 1024 + 2 * o]     = __float2half_rn(b2[idx]);
        Bs[i * 1104 + 1024 + 2 * o + 1] = __float2half_rn(root[idx]);
    }
    __syncthreads();

    int w = tid >> 5, lane = tid & 31;
    int g = lane >> 2, t = lane & 3;

    int ngroups = (N + 127) / 128;
    for (int grp = blockIdx.x; grp < ngroups; grp += gridDim.x) {
        int n0 = grp * 128 + w * 16;
        wmma::fragment<wmma::matrix_a, 16, 16, 16, __half, wmma::row_major> a0, a1;
        wmma::load_matrix_sync(a0, hA + (size_t)n0 * 32, 32);
        wmma::load_matrix_sync(a1, hA + (size_t)n0 * 32 + 16, 32);

        int r0 = n0 + g, r1 = n0 + g + 8;
        __half2* p0 = G2 + (size_t)r0 * 544 + t;
        __half2* p1 = G2 + (size_t)r1 * 544 + t;

#pragma unroll 4
        for (int jb = 0; jb < 68; jb++) {
            wmma::fragment<wmma::matrix_b, 16, 16, 16, __half, wmma::row_major> b0f, b1f;
            wmma::fragment<wmma::accumulator, 16, 16, 16, float> cf;
            wmma::fill_fragment(cf, 0.f);
            wmma::load_matrix_sync(b0f, Bs + jb * 16, 1104);
            wmma::load_matrix_sync(b1f, Bs + 16 * 1104 + jb * 16, 1104);
            wmma::mma_sync(cf, a0, b0f, cf);
            wmma::mma_sync(cf, a1, b1f, cf);
            // fp32 C frag: x0,x1=row g cols(2t,2t+1); x2,x3=row g+8; x4..7 = cols+8.
            int pc = jb * 8;
            if (r0 < N) {
                p0[pc]     = __floats2half2_rn(cf.x[0], cf.x[1]);
                p0[pc + 4] = __floats2half2_rn(cf.x[4], cf.x[5]);
            }
            if (r1 < N) {
                p1[pc]     = __floats2half2_rn(cf.x[2], cf.x[3]);
                p1[pc + 4] = __floats2half2_rn(cf.x[6], cf.x[7]);
            }
        }
    }
}

// ---------------- agg init: rootpart (G2 row16 .y) + bias -------------------
__global__ void k_agg_init(const __half2* __restrict__ G2, const float* __restrict__ bias,
                           float* __restrict__ agg, int N) {
    int idx = blockIdx.x * blockDim.x + threadIdx.x;
    if (idx >= N * 32) return;
    int n = idx >> 5, o = idx & 31;
    agg[idx] = __high2float(G2[(size_t)n * 544 + 512 + o]) + bias[o];
}

// ---------------- Kernel D: fused edge MLP + message, 2 edges per warp ------
// Lane roles in message phase: eh = lane>>4 selects edge (A/B), o2 = lane&15
// selects output pair (2*o2, 2*o2+1). Broadcast shuffles serve both edges.
__global__ void k_edge_msg(const int* __restrict__ ei, const float* __restrict__ ea,
                           const float* __restrict__ w1, const float* __restrict__ b1,
                           const __half2* __restrict__ G2, float* __restrict__ agg, int E) {
    int tid = threadIdx.x;
    int lane = tid & 31;
    int o2 = lane & 15, eh = lane >> 4;
    int warpg = (blockIdx.x * blockDim.x + tid) >> 5;

    float w1col[16];
#pragma unroll
    for (int j = 0; j < 16; j++) w1col[j] = __ldg(&w1[j * 32 + lane]);
    float b1l = __ldg(&b1[lane]);

    int ebase = warpg * (2 * NPAIR);
#pragma unroll
    for (int pp = 0; pp < NPAIR; pp++) {
        int eA = ebase + 2 * pp;
        if (eA >= E) return;
        int eB = eA + 1;
        bool hasB = (eB < E);

        int srcA = __ldg(&ei[eA]);
        int dstA = __ldg(&ei[E + eA]);
        int srcB = hasB ? __ldg(&ei[eB]) : srcA;
        int dstB = hasB ? __ldg(&ei[E + eB]) : dstA;

        // ---- MLP for edge A ----
        float eavA = (lane < 16) ? __ldg(&ea[(size_t)eA * 16 + lane]) : 0.f;
        float eaoA = __shfl_xor_sync(FULLMASK, eavA, 1);
        __half2 eA2 = (lane & 1) ? __floats2half2_rn(eaoA, eavA) : __floats2half2_rn(eavA, eaoA);
        unsigned euA = *(unsigned*)&eA2;
        float aA = b1l;
#pragma unroll
        for (int j = 0; j < 8; j++) {
            unsigned u = __shfl_sync(FULLMASK, euA, 2 * j);
            float2 f = __half22float2(*(__half2*)&u);
            aA = fmaf(f.x, w1col[2 * j], aA);
            aA = fmaf(f.y, w1col[2 * j + 1], aA);
        }
        float rvA = fmaxf(aA, 0.f);

        // ---- MLP for edge B ----
        float eavB = (hasB && lane < 16) ? __ldg(&ea[(size_t)eB * 16 + lane]) : 0.f;
        float eaoB = __shfl_xor_sync(FULLMASK, eavB, 1);
        __half2 eB2 = (lane & 1) ? __floats2half2_rn(eaoB, eavB) : __floats2half2_rn(eavB, eaoB);
        unsigned euB = *(unsigned*)&eB2;
        float aB = b1l;
#pragma unroll
        for (int j = 0; j < 8; j++) {
            unsigned u = __shfl_sync(FULLMASK, euB, 2 * j);
            float2 f = __half22float2(*(__half2*)&u);
            aB = fmaf(f.x, w1col[2 * j], aB);
            aB = fmaf(f.y, w1col[2 * j + 1], aB);
        }
        float rvB = fmaxf(aB, 0.f);

        // ---- combined pair register: lanes 0..15 hold edge A pair m=lane,
        //      lanes 16..31 hold edge B pair m=lane-16 ----
        float a0 = __shfl_sync(FULLMASK, rvA, 2 * o2);
        float a1 = __shfl_sync(FULLMASK, rvA, 2 * o2 + 1);
        float bb0 = __shfl_sync(FULLMASK, rvB, 2 * o2);
        float bb1 = __shfl_sync(FULLMASK, rvB, 2 * o2 + 1);
        __half2 crh = eh ? __floats2half2_rn(bb0, bb1) : __floats2half2_rn(a0, a1);
        unsigned cr = *(unsigned*)&crh;

        // ---- message for this lane's edge ----
        int src_e = eh ? srcB : srcA;
        const uint2* gp = (const uint2*)(G2 + (size_t)src_e * 544);
        uint2 hb = __ldg(&gp[256 + o2]);   // bias row: half2 for o=2o2 (x), 2o2+1 (y)
        float m0 = __low2float(*(__half2*)&hb.x);
        float m1 = __low2float(*(__half2*)&hb.y);
#pragma unroll
        for (int j = 0; j < 16; j++) {
            unsigned u = __shfl_sync(FULLMASK, cr, (lane & 16) + j);
            float2 r2 = __half22float2(*(__half2*)&u);
            uint2 gg = __ldg(&gp[j * 16 + o2]);
            float2 f0 = __half22float2(*(__half2*)&gg.x);   // output 2o2: (G[2j], G[2j+1])
            float2 f1 = __half22float2(*(__half2*)&gg.y);   // output 2o2+1
            m0 = fmaf(r2.x, f0.x, m0);
            m0 = fmaf(r2.y, f0.y, m0);
            m1 = fmaf(r2.x, f1.x, m1);
            m1 = fmaf(r2.y, f1.y, m1);
        }
        int dst_e = eh ? dstB : dstA;
        if (!eh || hasB) {
            float* ap = &agg[(size_t)dst_e * 32 + 2 * o2];
            asm volatile("red.global.add.v2.f32 [%0], {%1, %2};"
                         :: "l"(ap), "f"(m0), "f"(m1) : "memory");
        }
    }
}

// ---------------- Kernel E1: h = lrelu(agg) -> fp16 -------------------------
__global__ void k_act(const float* __restrict__ agg, __half* __restrict__ h, int total) {
    int idx = blockIdx.x * blockDim.x + threadIdx.x;
    if (idx >= total) return;
    h[idx] = __float2half_rn(lrelu(agg[idx]));
}

__global__ void k_zero(float* __restrict__ p, int total) {
    int idx = blockIdx.x * blockDim.x + threadIdx.x;
    if (idx < total) p[idx] = 0.f;
}

// ---------------- Kernel E2: atom_embs = lrelu(agg); pool into graphs -------
__global__ void k_act_pool(const float* __restrict__ agg, const int* __restrict__ batch,
                           float* __restrict__ atom_out, float* __restrict__ pooled, int N) {
    int idx = blockIdx.x * blockDim.x + threadIdx.x;
    if (idx >= N * 32) return;
    int n = idx >> 5;
    int o = idx & 31;
    float v = lrelu(agg[idx]);
    atom_out[idx] = v;
    atomicAdd(&pooled[batch[n] * 32 + o], v);
}

// ---------------- Kernel F: normalize pooled rows + final fc ----------------
__global__ void k_final(const float* __restrict__ pooled, const float* __restrict__ fcw,
                        const float* __restrict__ fcb, float* __restrict__ out, int G) {
    int warp = (blockIdx.x * blockDim.x + threadIdx.x) >> 5;
    int lane = threadIdx.x & 31;
    if (warp >= G) return;
    float p = pooled[warp * 32 + lane];
    float ss = p * p;
#pragma unroll
    for (int off = 16; off > 0; off >>= 1) ss += __shfl_xor_sync(FULLMASK, ss, off);
    float nrm = sqrtf(ss);
    float d = fmaxf(nrm, 1e-12f);
    float pn = p / d;
    float acc = fcb[lane];
#pragma unroll
    for (int jj = 0; jj < 32; jj++) {
        float pv = __shfl_sync(FULLMASK, pn, jj);
        acc = fmaf(pv, fcw[jj * 32 + lane], acc);
    }
    out[warp * 32 + lane] = acc;
}

extern "C" void kernel_launch(void* const* d_in, const int* in_sizes, int n_in,
                              void* d_out, int out_size) {
    const float* x        = (const float*)d_in[0];
    const int*   ei       = (const int*)  d_in[1];
    const float* ea       = (const float*)d_in[2];
    const int*   batch    = (const int*)  d_in[3];
    const float* nfc_w    = (const float*)d_in[5];
    const float* nfc_b    = (const float*)d_in[6];
    const float* e1w1     = (const float*)d_in[7];
    const float* e1b1     = (const float*)d_in[8];
    const float* e1w2     = (const float*)d_in[9];
    const float* e1b2     = (const float*)d_in[10];
    const float* root1    = (const float*)d_in[11];
    const float* bias1    = (const float*)d_in[12];
    const float* e2w1     = (const float*)d_in[13];
    const float* e2b1     = (const float*)d_in[14];
    const float* e2w2     = (const float*)d_in[15];
    const float* e2b2     = (const float*)d_in[16];
    const float* root2    = (const float*)d_in[17];
    const float* bias2    = (const float*)d_in[18];
    const float* fcw      = (const float*)d_in[19];
    const float* fcb      = (const float*)d_in[20];

    int N = in_sizes[0] / 64;
    int E = in_sizes[2] / 16;
    const int G = GMAX;

    float* outp = (float*)d_out;                 // [G,32]
    float* atom_out = (float*)d_out + G * 32;    // [N,32]

    __half *h0, *h1;
    float *agg, *pooled;
    __half2* G2;
    cudaGetSymbolAddress((void**)&h0,     g_h0);
    cudaGetSymbolAddress((void**)&h1,     g_h1);
    cudaGetSymbolAddress((void**)&G2,     g_G2);
    cudaGetSymbolAddress((void**)&agg,    g_agg);
    cudaGetSymbolAddress((void**)&pooled, g_pooled);

    const int smemC = 32 * 1104 * sizeof(__half);   // 70656 B
    cudaFuncSetAttribute(k_precompute_mma, cudaFuncAttributeMaxDynamicSharedMemorySize, smemC);

    int ngroups = (N + 127) / 128;
    int epb = 2 * NPAIR * 8;                        // edges per 256-thread block
    int egrid = (E + epb - 1) / epb;

    k_node_in<<<(N + 7) / 8, 256>>>(x, nfc_w, nfc_b, h0, N);

    // ---- layer 1 ----
    k_precompute_mma<<<ngroups, 256, smemC>>>(h0, e1w2, e1b2, root1, G2, N);
    k_agg_init<<<(N * 32 + 255) / 256, 256>>>(G2, bias1, agg, N);
    k_edge_msg<<<egrid, 256>>>(ei, ea, e1w1, e1b1, G2, agg, E);
    k_act<<<(N * 32 + 255) / 256, 256>>>(agg, h1, N * 32);

    // ---- layer 2 ----
    k_precompute_mma<<<ngroups, 256, smemC>>>(h1, e2w2, e2b2, root2, G2, N);
    k_agg_init<<<(N * 32 + 255) / 256, 256>>>(G2, bias2, agg, N);
    k_edge_msg<<<egrid, 256>>>(ei, ea, e2w1, e2b1, G2, agg, E);

    // pooling + outputs
    k_zero<<<(G * 32 + 255) / 256, 256>>>(pooled, G * 32);
    k_act_pool<<<(N * 32 + 255) / 256, 256>>>(agg, batch, atom_out, pooled, N);
    k_final<<<(G + 3) / 4, 128>>>(pooled, fcw, fcb, outp, G);
}

// round 16
// speedup vs baseline: 1.1870x; 1.0552x over previous
#include <cuda_runtime.h>
#include <cuda_fp16.h>
#include <mma.h>
#include <math.h>

using namespace nvcuda;

#define NMAX 20000
#define NPAD 20224          // 158 * 128
#define EMAX 200000
#define GMAX 128
#define DH   32
#define NPAIR 2             // edge-pairs per warp iteration (4 edges/warp)

__device__ __half  g_h0[NPAD * DH];            // fp16 node feats; padding rows stay zero
__device__ __half  g_h1[NPAD * DH];
__device__ __half2 g_G2[(size_t)NMAX * 544];   // [N][17][32] half2; pair j<16=(k=2j,2j+1); j=16=(biaspart, rootpart)
__device__ float   g_agg[NMAX * DH];
__device__ float   g_pooled[GMAX * DH];

#define FULLMASK 0xffffffffu

__device__ __forceinline__ float lrelu(float v) { return v > 0.f ? v : 0.01f * v; }

// ---------------- Kernel A: h0 = lrelu(x @ nfc_w + nfc_b) -> fp16 -----------
__global__ void k_node_in(const float* __restrict__ x, const float* __restrict__ w,
                          const float* __restrict__ b, __half* __restrict__ h0, int N) {
    int warp = (blockIdx.x * blockDim.x + threadIdx.x) >> 5;
    int lane = threadIdx.x & 31;
    if (warp >= N) return;
    const float* xr = x + (size_t)warp * 64;
    float x0 = xr[lane];
    float x1 = xr[32 + lane];
    float acc = b[lane];
#pragma unroll
    for (int i = 0; i < 32; i++) {
        float xv = __shfl_sync(FULLMASK, x0, i);
        acc = fmaf(xv, w[i * 32 + lane], acc);
    }
#pragma unroll
    for (int i = 0; i < 32; i++) {
        float xv = __shfl_sync(FULLMASK, x1, i);
        acc = fmaf(xv, w[(32 + i) * 32 + lane], acc);
    }
    h0[warp * 32 + lane] = __float2half_rn(lrelu(acc));
}

// ---------------- Kernel C: tensor-core precompute of G2 + fused agg init ---
// Hot loop jb<64 unchanged (branch-free). Tail loop jb=64..67 (bias/root
// columns) writes the G2 bias row AND agg = rootpart(fp32) + bias.
__global__ void k_precompute_mma(const __half* __restrict__ hA,
                                 const float* __restrict__ w2, const float* __restrict__ b2,
                                 const float* __restrict__ root, const float* __restrict__ bias,
                                 __half2* __restrict__ G2, float* __restrict__ agg, int N) {
    extern __shared__ __half Bs[];   // [32][1104] halves + 32 floats bias
    float* biass = (float*)(Bs + 32 * 1104);
    int tid = threadIdx.x;
    for (int idx = tid; idx < 32 * 1024; idx += 256) {
        int k = idx >> 10;              // w2 row 0..31
        int rem = idx & 1023;
        int i = rem >> 5, o = rem & 31;
        int m = (k >> 1) * 64 + 2 * o + (k & 1);
        Bs[i * 1104 + m] = __float2half_rn(w2[idx]);   // coalesced read
    }
    for (int idx = tid; idx < 1024; idx += 256) {
        int i = idx >> 5, o = idx & 31;
        Bs[i * 1104 + 1024 + 2 * o]     = __float2half_rn(b2[idx]);
        Bs[i * 1104 + 1024 + 2 * o + 1] = __float2half_rn(root[idx]);
    }
    if (tid < 32) biass[tid] = bias[tid];
    __syncthreads();

    int w = tid >> 5, lane = tid & 31;
    int g = lane >> 2, t = lane & 3;

    int ngroups = (N + 127) / 128;
    for (int grp = blockIdx.x; grp < ngroups; grp += gridDim.x) {
        int n0 = grp * 128 + w * 16;
        wmma::fragment<wmma::matrix_a, 16, 16, 16, __half, wmma::row_major> a0, a1;
        wmma::load_matrix_sync(a0, hA + (size_t)n0 * 32, 32);
        wmma::load_matrix_sync(a1, hA + (size_t)n0 * 32 + 16, 32);

        int r0 = n0 + g, r1 = n0 + g + 8;
        __half2* p0 = G2 + (size_t)r0 * 544 + t;
        __half2* p1 = G2 + (size_t)r1 * 544 + t;

#pragma unroll 4
        for (int jb = 0; jb < 64; jb++) {
            wmma::fragment<wmma::matrix_b, 16, 16, 16, __half, wmma::row_major> b0f, b1f;
            wmma::fragment<wmma::accumulator, 16, 16, 16, float> cf;
            wmma::fill_fragment(cf, 0.f);
            wmma::load_matrix_sync(b0f, Bs + jb * 16, 1104);
            wmma::load_matrix_sync(b1f, Bs + 16 * 1104 + jb * 16, 1104);
            wmma::mma_sync(cf, a0, b0f, cf);
            wmma::mma_sync(cf, a1, b1f, cf);
            // fp32 C frag: x0,x1=row g cols(2t,2t+1); x2,x3=row g+8; x4..7 = cols+8.
            int pc = jb * 8;
            if (r0 < N) {
                p0[pc]     = __floats2half2_rn(cf.x[0], cf.x[1]);
                p0[pc + 4] = __floats2half2_rn(cf.x[4], cf.x[5]);
            }
            if (r1 < N) {
                p1[pc]     = __floats2half2_rn(cf.x[2], cf.x[3]);
                p1[pc + 4] = __floats2half2_rn(cf.x[6], cf.x[7]);
            }
        }
        // tail: bias/root blocks -> G2 bias row + agg init (fp32 root + bias)
#pragma unroll
        for (int jb = 64; jb < 68; jb++) {
            wmma::fragment<wmma::matrix_b, 16, 16, 16, __half, wmma::row_major> b0f, b1f;
            wmma::fragment<wmma::accumulator, 16, 16, 16, float> cf;
            wmma::fill_fragment(cf, 0.f);
            wmma::load_matrix_sync(b0f, Bs + jb * 16, 1104);
            wmma::load_matrix_sync(b1f, Bs + 16 * 1104 + jb * 16, 1104);
            wmma::mma_sync(cf, a0, b0f, cf);
            wmma::mma_sync(cf, a1, b1f, cf);
            int pc = jb * 8;
            int o0 = pc + t - 512;           // 0..27 (+4 sibling)
            if (r0 < N) {
                p0[pc]     = __floats2half2_rn(cf.x[0], cf.x[1]);
                p0[pc + 4] = __floats2half2_rn(cf.x[4], cf.x[5]);
                agg[(size_t)r0 * 32 + o0]     = cf.x[1] + biass[o0];
                agg[(size_t)r0 * 32 + o0 + 4] = cf.x[5] + biass[o0 + 4];
            }
            if (r1 < N) {
                p1[pc]     = __floats2half2_rn(cf.x[2], cf.x[3]);
                p1[pc + 4] = __floats2half2_rn(cf.x[6], cf.x[7]);
                agg[(size_t)r1 * 32 + o0]     = cf.x[3] + biass[o0];
                agg[(size_t)r1 * 32 + o0 + 4] = cf.x[7] + biass[o0 + 4];
            }
        }
    }
}

// ---------------- Kernel D: fused edge MLP + message, 2 edges per warp ------
__global__ void k_edge_msg(const int* __restrict__ ei, const float* __restrict__ ea,
                           const float* __restrict__ w1, const float* __restrict__ b1,
                           const __half2* __restrict__ G2, float* __restrict__ agg, int E) {
    int tid = threadIdx.x;
    int lane = tid & 31;
    int o2 = lane & 15, eh = lane >> 4;
    int warpg = (blockIdx.x * blockDim.x + tid) >> 5;

    float w1col[16];
#pragma unroll
    for (int j = 0; j < 16; j++) w1col[j] = __ldg(&w1[j * 32 + lane]);
    float b1l = __ldg(&b1[lane]);

    int ebase = warpg * (2 * NPAIR);
#pragma unroll
    for (int pp = 0; pp < NPAIR; pp++) {
        int eA = ebase + 2 * pp;
        if (eA >= E) return;
        int eB = eA + 1;
        bool hasB = (eB < E);

        int srcA = __ldg(&ei[eA]);
        int dstA = __ldg(&ei[E + eA]);
        int srcB = hasB ? __ldg(&ei[eB]) : srcA;
        int dstB = hasB ? __ldg(&ei[E + eB]) : dstA;

        // ---- MLP for edge A (two accumulators for ILP) ----
        float eavA = (lane < 16) ? __ldg(&ea[(size_t)eA * 16 + lane]) : 0.f;
        float eaoA = __shfl_xor_sync(FULLMASK, eavA, 1);
        __half2 eA2 = (lane & 1) ? __floats2half2_rn(eaoA, eavA) : __floats2half2_rn(eavA, eaoA);
        unsigned euA = *(unsigned*)&eA2;
        float aA = b1l, aA2 = 0.f;
#pragma unroll
        for (int j = 0; j < 8; j++) {
            unsigned u = __shfl_sync(FULLMASK, euA, 2 * j);
            float2 f = __half22float2(*(__half2*)&u);
            aA  = fmaf(f.x, w1col[2 * j], aA);
            aA2 = fmaf(f.y, w1col[2 * j + 1], aA2);
        }
        float rvA = fmaxf(aA + aA2, 0.f);

        // ---- MLP for edge B ----
        float eavB = (hasB && lane < 16) ? __ldg(&ea[(size_t)eB * 16 + lane]) : 0.f;
        float eaoB = __shfl_xor_sync(FULLMASK, eavB, 1);
        __half2 eB2 = (lane & 1) ? __floats2half2_rn(eaoB, eavB) : __floats2half2_rn(eavB, eaoB);
        unsigned euB = *(unsigned*)&eB2;
        float aB = b1l, aB2 = 0.f;
#pragma unroll
        for (int j = 0; j < 8; j++) {
            unsigned u = __shfl_sync(FULLMASK, euB, 2 * j);
            float2 f = __half22float2(*(__half2*)&u);
            aB  = fmaf(f.x, w1col[2 * j], aB);
            aB2 = fmaf(f.y, w1col[2 * j + 1], aB2);
        }
        float rvB = fmaxf(aB + aB2, 0.f);

        // ---- combined pair register: lanes 0..15 edge A pair m=lane,
        //      lanes 16..31 edge B pair m=lane-16 ----
        float a0 = __shfl_sync(FULLMASK, rvA, 2 * o2);
        float a1 = __shfl_sync(FULLMASK, rvA, 2 * o2 + 1);
        float bb0 = __shfl_sync(FULLMASK, rvB, 2 * o2);
        float bb1 = __shfl_sync(FULLMASK, rvB, 2 * o2 + 1);
        __half2 crh = eh ? __floats2half2_rn(bb0, bb1) : __floats2half2_rn(a0, a1);
        unsigned cr = *(unsigned*)&crh;

        // ---- message for this lane's edge ----
        int src_e = eh ? srcB : srcA;
        const uint2* gp = (const uint2*)(G2 + (size_t)src_e * 544);
        uint2 hb = __ldg(&gp[256 + o2]);   // bias row half2s for o=2o2 (x), 2o2+1 (y)
        float m0 = __low2float(*(__half2*)&hb.x);
        float m1 = __low2float(*(__half2*)&hb.y);
#pragma unroll
        for (int j = 0; j < 16; j++) {
            unsigned u = __shfl_sync(FULLMASK, cr, (lane & 16) + j);
            float2 r2 = __half22float2(*(__half2*)&u);
            uint2 gg = __ldg(&gp[j * 16 + o2]);
            float2 f0 = __half22float2(*(__half2*)&gg.x);
            float2 f1 = __half22float2(*(__half2*)&gg.y);
            m0 = fmaf(r2.x, f0.x, m0);
            m0 = fmaf(r2.y, f0.y, m0);
            m1 = fmaf(r2.x, f1.x, m1);
            m1 = fmaf(r2.y, f1.y, m1);
        }
        int dst_e = eh ? dstB : dstA;
        if (!eh || hasB) {
            float* ap = &agg[(size_t)dst_e * 32 + 2 * o2];
            asm volatile("red.global.add.v2.f32 [%0], {%1, %2};"
                         :: "l"(ap), "f"(m0), "f"(m1) : "memory");
        }
    }
}

// ---------------- Kernel E1: h = lrelu(agg) -> fp16 -------------------------
__global__ void k_act(const float* __restrict__ agg, __half* __restrict__ h, int total) {
    int idx = blockIdx.x * blockDim.x + threadIdx.x;
    if (idx >= total) return;
    h[idx] = __float2half_rn(lrelu(agg[idx]));
}

__global__ void k_zero(float* __restrict__ p, int total) {
    int idx = blockIdx.x * blockDim.x + threadIdx.x;
    if (idx < total) p[idx] = 0.f;
}

// ---------------- Kernel E2: atom_embs = lrelu(agg); pool into graphs -------
__global__ void k_act_pool(const float* __restrict__ agg, const int* __restrict__ batch,
                           float* __restrict__ atom_out, float* __restrict__ pooled, int N) {
    int idx = blockIdx.x * blockDim.x + threadIdx.x;
    if (idx >= N * 32) return;
    int n = idx >> 5;
    int o = idx & 31;
    float v = lrelu(agg[idx]);
    atom_out[idx] = v;
    atomicAdd(&pooled[batch[n] * 32 + o], v);
}

// ---------------- Kernel F: normalize pooled rows + final fc ----------------
__global__ void k_final(const float* __restrict__ pooled, const float* __restrict__ fcw,
                        const float* __restrict__ fcb, float* __restrict__ out, int G) {
    int warp = (blockIdx.x * blockDim.x + threadIdx.x) >> 5;
    int lane = threadIdx.x & 31;
    if (warp >= G) return;
    float p = pooled[warp * 32 + lane];
    float ss = p * p;
#pragma unroll
    for (int off = 16; off > 0; off >>= 1) ss += __shfl_xor_sync(FULLMASK, ss, off);
    float nrm = sqrtf(ss);
    float d = fmaxf(nrm, 1e-12f);
    float pn = p / d;
    float acc = fcb[lane];
#pragma unroll
    for (int jj = 0; jj < 32; jj++) {
        float pv = __shfl_sync(FULLMASK, pn, jj);
        acc = fmaf(pv, fcw[jj * 32 + lane], acc);
    }
    out[warp * 32 + lane] = acc;
}

extern "C" void kernel_launch(void* const* d_in, const int* in_sizes, int n_in,
                              void* d_out, int out_size) {
    const float* x        = (const float*)d_in[0];
    const int*   ei       = (const int*)  d_in[1];
    const float* ea       = (const float*)d_in[2];
    const int*   batch    = (const int*)  d_in[3];
    const float* nfc_w    = (const float*)d_in[5];
    const float* nfc_b    = (const float*)d_in[6];
    const float* e1w1     = (const float*)d_in[7];
    const float* e1b1     = (const float*)d_in[8];
    const float* e1w2     = (const float*)d_in[9];
    const float* e1b2     = (const float*)d_in[10];
    const float* root1    = (const float*)d_in[11];
    const float* bias1    = (const float*)d_in[12];
    const float* e2w1     = (const float*)d_in[13];
    const float* e2b1     = (const float*)d_in[14];
    const float* e2w2     = (const float*)d_in[15];
    const float* e2b2     = (const float*)d_in[16];
    const float* root2    = (const float*)d_in[17];
    const float* bias2    = (const float*)d_in[18];
    const float* fcw      = (const float*)d_in[19];
    const float* fcb      = (const float*)d_in[20];

    int N = in_sizes[0] / 64;
    int E = in_sizes[2] / 16;
    const int G = GMAX;

    float* outp = (float*)d_out;                 // [G,32]
    float* atom_out = (float*)d_out + G * 32;    // [N,32]

    __half *h0, *h1;
    float *agg, *pooled;
    __half2* G2;
    cudaGetSymbolAddress((void**)&h0,     g_h0);
    cudaGetSymbolAddress((void**)&h1,     g_h1);
    cudaGetSymbolAddress((void**)&G2,     g_G2);
    cudaGetSymbolAddress((void**)&agg,    g_agg);
    cudaGetSymbolAddress((void**)&pooled, g_pooled);

    const int smemC = 32 * 1104 * sizeof(__half) + 32 * sizeof(float);   // 70784 B
    cudaFuncSetAttribute(k_precompute_mma, cudaFuncAttributeMaxDynamicSharedMemorySize, smemC);

    int ngroups = (N + 127) / 128;
    int epb = 2 * NPAIR * 8;                        // edges per 256-thread block
    int egrid = (E + epb - 1) / epb;

    k_node_in<<<(N + 7) / 8, 256>>>(x, nfc_w, nfc_b, h0, N);

    // ---- layer 1 ----
    k_precompute_mma<<<ngroups, 256, smemC>>>(h0, e1w2, e1b2, root1, bias1, G2, agg, N);
    k_edge_msg<<<egrid, 256>>>(ei, ea, e1w1, e1b1, G2, agg, E);
    k_act<<<(N * 32 + 255) / 256, 256>>>(agg, h1, N * 32);

    // ---- layer 2 ----
    k_precompute_mma<<<ngroups, 256, smemC>>>(h1, e2w2, e2b2, root2, bias2, G2, agg, N);
    k_edge_msg<<<egrid, 256>>>(ei, ea, e2w1, e2b1, G2, agg, E);

    // pooling + outputs
    k_zero<<<(G * 32 + 255) / 256, 256>>>(pooled, G * 32);
    k_act_pool<<<(N * 32 + 255) / 256, 256>>>(agg, batch, atom_out, pooled, N);
    k_final<<<(G + 3) / 4, 128>>>(pooled, fcw, fcb, outp, G);
}